// round 3
// baseline (speedup 1.0000x reference)
#include <cuda_runtime.h>
#include <cuda_bf16.h>
#include <math.h>

// ---------------- problem constants ----------------
#define BB 2
#define NN_NODES 512
#define FDIM 1024
#define HEADS 4
#define DH 256
#define AH 256
#define HID 512
#define OUTF 128
#define NCLS 10
#define NN2 (NN_NODES*NN_NODES)          // 262144
#define KSEL 209715                       // int(0.8 * N*N)
#define THR_IDX (NN2 - KSEL)              // 52429 (0-based ascending rank)
#define BN_M (BB*NN_NODES)
#define PJOFF (BB*NN_NODES*AH)

// ---------------- device scratch ----------------
__device__ float g_hp [BB*NN_NODES*FDIM];
__device__ float g_nf [BB*NN_NODES*FDIM];
__device__ float g_si [BB*HEADS*NN_NODES];
__device__ float g_sj [BB*HEADS*NN_NODES];
__device__ float g_pij[2*BB*NN_NODES*AH];
__device__ float g_sc [BB*NN2];               // raw scores (already /TEMP)
__device__ float g_adj[BB*NN2];               // kept exp values (unnormalized)
__device__ float g_h1 [BB*NN_NODES*FDIM];
__device__ float g_h1b[BB*NN_NODES*HID];
__device__ float g_h2 [BB*NN_NODES*HID];
__device__ float g_h2b[BB*NN_NODES*OUTF];
__device__ float g_part[BB*64];
__device__ float g_inv[BB];
__device__ unsigned g_mxu[BB];
__device__ unsigned g_h16[BB][65536];
__device__ unsigned g_hi16[BB];
__device__ int g_selrank[BB];
__device__ unsigned g_thrE[BB];

// ---------------- helpers ----------------
__device__ __forceinline__ float f2tf32f(float x) {
    unsigned r;
    asm("cvt.rna.tf32.f32 %0, %1;" : "=r"(r) : "f"(x));
    return __uint_as_float(r);
}
__device__ __forceinline__ unsigned enc_f(float f) {
    unsigned u = __float_as_uint(f);
    return (u & 0x80000000u) ? ~u : (u | 0x80000000u);
}
__device__ __forceinline__ float dec_f(unsigned e) {
    unsigned u = (e & 0x80000000u) ? (e ^ 0x80000000u) : ~e;
    return __uint_as_float(u);
}

// ---------------- 3xTF32 tensor-core GEMM ----------------
// C[m,n] = sum_k A[m,k] * (TRANSB ? B[n,k] : B[k,n])  (+bias[n]) (*scale[z])
// 128 threads, tile 64x64, K-tile 32, single-buffered smem + register staging.
#define APITCH 36
#define BPITCH 68
template<bool TRANSB, bool BIAS, bool SCALE>
__global__ void __launch_bounds__(128) mma_gemm(
    const float* __restrict__ A, int lda, long sA,
    const float* __restrict__ Bm, int ldb, long sB,
    const float* __restrict__ bias, const float* __restrict__ scale,
    float* __restrict__ C, int ldc, long sC, int K)
{
    __shared__ float Ah[64 * APITCH];
    __shared__ float Al[64 * APITCH];
    __shared__ float Bh[32 * BPITCH];
    __shared__ float Bl[32 * BPITCH];

    const int bz = blockIdx.z;
    A  += (long)bz * sA;
    Bm += (long)bz * sB;
    C  += (long)bz * sC;
    const int m0 = blockIdx.y * 64;
    const int n0 = blockIdx.x * 64;
    const int tid = threadIdx.x;
    const int lane = tid & 31;
    const int wid  = tid >> 5;
    const int wm = wid >> 1, wn = wid & 1;
    const int g  = lane >> 2;
    const int tg = lane & 3;

    const int a_mr = tid >> 3;
    const int a_k4 = tid & 7;
    const int bt_nr = tid >> 3;
    const int bt_k4 = tid & 7;
    const int bn_kr = tid >> 4;
    const int bn_n4 = tid & 15;

    float acc[2][4][4];
#pragma unroll
    for (int im = 0; im < 2; im++)
#pragma unroll
        for (int in = 0; in < 4; in++)
#pragma unroll
            for (int q = 0; q < 4; q++) acc[im][in][q] = 0.f;

    const int niter = K >> 5;
    float4 ra[4], rb[4];

    auto load_regs = [&](int k0) {
#pragma unroll
        for (int i = 0; i < 4; i++) {
            int m = a_mr + 16 * i;
            ra[i] = *(const float4*)&A[(long)(m0 + m) * lda + k0 + a_k4 * 4];
        }
        if (TRANSB) {
#pragma unroll
            for (int i = 0; i < 4; i++) {
                int n = bt_nr + 16 * i;
                rb[i] = *(const float4*)&Bm[(long)(n0 + n) * ldb + k0 + bt_k4 * 4];
            }
        } else {
#pragma unroll
            for (int i = 0; i < 4; i++) {
                int kk = bn_kr + 8 * i;
                rb[i] = *(const float4*)&Bm[(long)(k0 + kk) * ldb + n0 + bn_n4 * 4];
            }
        }
    };
    auto store_smem = [&]() {
#pragma unroll
        for (int i = 0; i < 4; i++) {
            int m = a_mr + 16 * i;
            float4 v = ra[i];
            float4 h = make_float4(f2tf32f(v.x), f2tf32f(v.y), f2tf32f(v.z), f2tf32f(v.w));
            float4 l = make_float4(f2tf32f(v.x - h.x), f2tf32f(v.y - h.y),
                                   f2tf32f(v.z - h.z), f2tf32f(v.w - h.w));
            *(float4*)&Ah[m * APITCH + a_k4 * 4] = h;
            *(float4*)&Al[m * APITCH + a_k4 * 4] = l;
        }
        if (TRANSB) {
#pragma unroll
            for (int i = 0; i < 4; i++) {
                int n = bt_nr + 16 * i;
                float4 v = rb[i];
                float hx = f2tf32f(v.x), hy = f2tf32f(v.y), hz = f2tf32f(v.z), hw = f2tf32f(v.w);
                Bh[(bt_k4 * 4 + 0) * BPITCH + n] = hx;
                Bh[(bt_k4 * 4 + 1) * BPITCH + n] = hy;
                Bh[(bt_k4 * 4 + 2) * BPITCH + n] = hz;
                Bh[(bt_k4 * 4 + 3) * BPITCH + n] = hw;
                Bl[(bt_k4 * 4 + 0) * BPITCH + n] = f2tf32f(v.x - hx);
                Bl[(bt_k4 * 4 + 1) * BPITCH + n] = f2tf32f(v.y - hy);
                Bl[(bt_k4 * 4 + 2) * BPITCH + n] = f2tf32f(v.z - hz);
                Bl[(bt_k4 * 4 + 3) * BPITCH + n] = f2tf32f(v.w - hw);
            }
        } else {
#pragma unroll
            for (int i = 0; i < 4; i++) {
                int kk = bn_kr + 8 * i;
                float4 v = rb[i];
                float4 h = make_float4(f2tf32f(v.x), f2tf32f(v.y), f2tf32f(v.z), f2tf32f(v.w));
                float4 l = make_float4(f2tf32f(v.x - h.x), f2tf32f(v.y - h.y),
                                       f2tf32f(v.z - h.z), f2tf32f(v.w - h.w));
                *(float4*)&Bh[kk * BPITCH + bn_n4 * 4] = h;
                *(float4*)&Bl[kk * BPITCH + bn_n4 * 4] = l;
            }
        }
    };

#define MMA_OP(d, a0,a1,a2,a3, b0,b1)                                        \
    asm volatile("mma.sync.aligned.m16n8k8.row.col.f32.tf32.tf32.f32 "       \
                 "{%0,%1,%2,%3}, {%4,%5,%6,%7}, {%8,%9}, {%0,%1,%2,%3};"     \
                 : "+f"(d[0]), "+f"(d[1]), "+f"(d[2]), "+f"(d[3])            \
                 : "r"(a0), "r"(a1), "r"(a2), "r"(a3), "r"(b0), "r"(b1))

    load_regs(0);
    for (int it = 0; it < niter; it++) {
        store_smem();
        __syncthreads();
        if (it + 1 < niter) load_regs((it + 1) << 5);

#pragma unroll
        for (int ks = 0; ks < 4; ks++) {
            unsigned afh[2][4], afl[2][4];
#pragma unroll
            for (int im = 0; im < 2; im++) {
                int mb = wm * 32 + im * 16;
                afh[im][0] = __float_as_uint(Ah[(mb + g) * APITCH + ks * 8 + tg]);
                afh[im][1] = __float_as_uint(Ah[(mb + 8 + g) * APITCH + ks * 8 + tg]);
                afh[im][2] = __float_as_uint(Ah[(mb + g) * APITCH + ks * 8 + 4 + tg]);
                afh[im][3] = __float_as_uint(Ah[(mb + 8 + g) * APITCH + ks * 8 + 4 + tg]);
                afl[im][0] = __float_as_uint(Al[(mb + g) * APITCH + ks * 8 + tg]);
                afl[im][1] = __float_as_uint(Al[(mb + 8 + g) * APITCH + ks * 8 + tg]);
                afl[im][2] = __float_as_uint(Al[(mb + g) * APITCH + ks * 8 + 4 + tg]);
                afl[im][3] = __float_as_uint(Al[(mb + 8 + g) * APITCH + ks * 8 + 4 + tg]);
            }
            unsigned bfh[4][2], bfl[4][2];
#pragma unroll
            for (int in = 0; in < 4; in++) {
                int nb = wn * 32 + in * 8;
                bfh[in][0] = __float_as_uint(Bh[(ks * 8 + tg) * BPITCH + nb + g]);
                bfh[in][1] = __float_as_uint(Bh[(ks * 8 + 4 + tg) * BPITCH + nb + g]);
                bfl[in][0] = __float_as_uint(Bl[(ks * 8 + tg) * BPITCH + nb + g]);
                bfl[in][1] = __float_as_uint(Bl[(ks * 8 + 4 + tg) * BPITCH + nb + g]);
            }
#pragma unroll
            for (int im = 0; im < 2; im++)
#pragma unroll
                for (int in = 0; in < 4; in++) {
                    MMA_OP(acc[im][in], afl[im][0], afl[im][1], afl[im][2], afl[im][3],
                           bfh[in][0], bfh[in][1]);
                    MMA_OP(acc[im][in], afh[im][0], afh[im][1], afh[im][2], afh[im][3],
                           bfl[in][0], bfl[in][1]);
                    MMA_OP(acc[im][in], afh[im][0], afh[im][1], afh[im][2], afh[im][3],
                           bfh[in][0], bfh[in][1]);
                }
        }
        __syncthreads();
    }

    float scv = SCALE ? scale[bz] : 1.f;
#pragma unroll
    for (int im = 0; im < 2; im++) {
        int r0 = m0 + wm * 32 + im * 16 + g;
        int r1 = r0 + 8;
#pragma unroll
        for (int in = 0; in < 4; in++) {
            int c = n0 + wn * 32 + in * 8 + 2 * tg;
            float b0 = 0.f, b1v = 0.f;
            if (BIAS) { b0 = bias[c]; b1v = bias[c + 1]; }
            float2 v0, v1;
            if (SCALE) {
                v0 = make_float2(acc[im][in][0] * scv, acc[im][in][1] * scv);
                v1 = make_float2(acc[im][in][2] * scv, acc[im][in][3] * scv);
            } else {
                v0 = make_float2(acc[im][in][0] + b0, acc[im][in][1] + b1v);
                v1 = make_float2(acc[im][in][2] + b0, acc[im][in][3] + b1v);
            }
            *(float2*)&C[(long)r0 * ldc + c] = v0;
            *(float2*)&C[(long)r1 * ldc + c] = v1;
        }
    }
#undef MMA_OP
}

// ---------------- init (clear histograms + max) ----------------
__global__ void init_kernel()
{
    int idx = blockIdx.x * 1024 + threadIdx.x;   // grid 128 x 1024 = 131072
    int b = idx >> 16, bin = idx & 65535;
    g_h16[b][bin] = 0u;
    if (idx < BB) g_mxu[idx] = 0u;
}

// ---------------- s_i, s_j ----------------
__global__ void sij_kernel(const float* __restrict__ attn)
{
    int gw = (blockIdx.x * blockDim.x + threadIdx.x) >> 5;
    int lane = threadIdx.x & 31;
    if (gw >= BB * HEADS * NN_NODES) return;
    int b = gw / (HEADS * NN_NODES);
    int r = gw % (HEADS * NN_NODES);
    int h = r / NN_NODES;
    int n = r % NN_NODES;
    const float* hp = g_hp + ((long)(b * NN_NODES + n)) * FDIM + h * DH;
    const float* ai = attn + h * 2 * DH;
    float si = 0.f, sj = 0.f;
#pragma unroll
    for (int d = lane; d < DH; d += 32) {
        float v = hp[d];
        si += v * ai[d];
        sj += v * ai[DH + d];
    }
#pragma unroll
    for (int o = 16; o > 0; o >>= 1) {
        si += __shfl_down_sync(0xffffffffu, si, o);
        sj += __shfl_down_sync(0xffffffffu, sj, o);
    }
    if (lane == 0) { g_si[gw] = si; g_sj[gw] = sj; }
}

// ---------------- fused attention softmax + aggregation ----------------
#define WPITCH 20
__global__ void attn_kernel()
{
    __shared__ float sj[NN_NODES];
    __shared__ float ws[NN_NODES * WPITCH];
    __shared__ float red[8];
    int bh = blockIdx.y;
    int b = bh / HEADS, h = bh % HEADS;
    int i0 = blockIdx.x * 16;
    int tid = threadIdx.x;

    for (int j = tid; j < NN_NODES; j += 256) sj[j] = g_sj[bh * NN_NODES + j];
    __syncthreads();

    float mx = -3.4e38f;
    for (int j = tid; j < NN_NODES; j += 256) mx = fmaxf(mx, sj[j]);
#pragma unroll
    for (int o = 16; o > 0; o >>= 1) mx = fmaxf(mx, __shfl_xor_sync(0xffffffffu, mx, o));
    if ((tid & 31) == 0) red[tid >> 5] = mx;
    __syncthreads();
    if (tid == 0) {
        float m = red[0];
        for (int q = 1; q < 8; q++) m = fmaxf(m, red[q]);
        red[0] = m;
    }
    __syncthreads();
    float sjmax = red[0];

    int wi = tid >> 5, lane = tid & 31;
#pragma unroll
    for (int rr = 0; rr < 2; rr++) {
        int r = wi * 2 + rr;
        int i = i0 + r;
        float si = g_si[bh * NN_NODES + i];
        float M = si + sjmax;
        M = (M >= 0.f) ? M : 0.2f * M;
        float sum = 0.f;
        for (int j = lane; j < NN_NODES; j += 32) {
            float e = si + sj[j];
            e = (e >= 0.f) ? e : 0.2f * e;
            float p = expf(e - M);
            ws[j * WPITCH + r] = p;
            sum += p;
        }
#pragma unroll
        for (int o = 16; o > 0; o >>= 1) sum += __shfl_xor_sync(0xffffffffu, sum, o);
        float inv = 1.0f / sum;
        for (int j = lane; j < NN_NODES; j += 32) ws[j * WPITCH + r] *= inv;
    }
    __syncthreads();

    int d = tid;
    const float* hpp = g_hp + (long)(b * NN_NODES) * FDIM + h * DH + d;
    float acc[16];
#pragma unroll
    for (int r = 0; r < 16; r++) acc[r] = 0.f;
#pragma unroll 2
    for (int j = 0; j < NN_NODES; j++) {
        float v = hpp[(long)j * FDIM];
        const float4* wr = (const float4*)&ws[j * WPITCH];
        float4 a0 = wr[0], a1 = wr[1], a2 = wr[2], a3 = wr[3];
        acc[0]  += a0.x * v; acc[1]  += a0.y * v; acc[2]  += a0.z * v; acc[3]  += a0.w * v;
        acc[4]  += a1.x * v; acc[5]  += a1.y * v; acc[6]  += a1.z * v; acc[7]  += a1.w * v;
        acc[8]  += a2.x * v; acc[9]  += a2.y * v; acc[10] += a2.z * v; acc[11] += a2.w * v;
        acc[12] += a3.x * v; acc[13] += a3.y * v; acc[14] += a3.z * v; acc[15] += a3.w * v;
    }
#pragma unroll
    for (int r = 0; r < 16; r++)
        g_nf[((long)(b * NN_NODES) + i0 + r) * FDIM + h * DH + d] = acc[r];
}

// ---------------- edge MLP scores + global max ----------------
__global__ void edge_kernel(const float* __restrict__ b1,
                            const float* __restrict__ w2,
                            const float* __restrict__ b2p)
{
    __shared__ float spi[16][260];
    __shared__ float spj[16][260];
    __shared__ float sw2[AH];
    __shared__ float red[256];
    int b = blockIdx.z;
    int i0 = blockIdx.y * 16, j0 = blockIdx.x * 16;
    int tid = threadIdx.x;

    float b1v = b1[tid];
    sw2[tid] = w2[tid];
#pragma unroll
    for (int l = 0; l < 16; l++) {
        spi[l][tid] = g_pij[((long)(b * NN_NODES) + i0 + l) * AH + tid] + b1v;
        spj[l][tid] = g_pij[PJOFF + ((long)(b * NN_NODES) + j0 + l) * AH + tid];
    }
    __syncthreads();
    int ti = tid >> 4, tj = tid & 15;
    float acc = 0.f;
#pragma unroll
    for (int a = 0; a < AH; a += 4) {
        float4 p4 = *(const float4*)&spi[ti][a];
        float4 q4 = *(const float4*)&spj[tj][a];
        float4 w4 = *(const float4*)&sw2[a];
        acc += fmaxf(p4.x + q4.x, 0.f) * w4.x;
        acc += fmaxf(p4.y + q4.y, 0.f) * w4.y;
        acc += fmaxf(p4.z + q4.z, 0.f) * w4.z;
        acc += fmaxf(p4.w + q4.w, 0.f) * w4.w;
    }
    float sc = (acc + b2p[0]) * 2.0f;   // /TEMP
    g_sc[(long)b * NN2 + (long)(i0 + ti) * NN_NODES + (j0 + tj)] = sc;

    red[tid] = sc;
    __syncthreads();
    for (int s = 128; s > 0; s >>= 1) {
        if (tid < s) red[tid] = fmaxf(red[tid], red[tid + s]);
        __syncthreads();
    }
    if (tid == 0) atomicMax(&g_mxu[b], enc_f(red[0]));
}

// ---------------- 2-level radix select on encoded scores ----------------
__global__ void histA_kernel()
{
    int b = blockIdx.y, blk = blockIdx.x, tid = threadIdx.x;
    const float* sm = g_sc + (long)b * NN2;
    for (int i = blk * 256 + tid; i < NN2; i += 32 * 256) {
        unsigned e = enc_f(sm[i]);
        atomicAdd(&g_h16[b][e >> 16], 1u);
    }
}
__global__ void histB_kernel()
{
    int b = blockIdx.y, blk = blockIdx.x, tid = threadIdx.x;
    unsigned hi = g_hi16[b];
    const float* sm = g_sc + (long)b * NN2;
    for (int i = blk * 256 + tid; i < NN2; i += 32 * 256) {
        unsigned e = enc_f(sm[i]);
        if ((e >> 16) == hi) atomicAdd(&g_h16[b][e & 0xFFFFu], 1u);
    }
}
__global__ void pick_kernel(int phase)
{
    __shared__ unsigned part[1024];
    __shared__ unsigned wsum[32];
    __shared__ int s_warp, s_thread;
    __shared__ unsigned s_base, s_base2;
    int b = blockIdx.x, tid = threadIdx.x, lane = tid & 31, wrp = tid >> 5;
    unsigned* bins = g_h16[b];
    unsigned rank = (phase == 0) ? (unsigned)THR_IDX : (unsigned)g_selrank[b];

    unsigned s = 0;
#pragma unroll 8
    for (int t = 0; t < 64; t++) s += bins[tid * 64 + t];
    part[tid] = s;
    unsigned wsv = s;
#pragma unroll
    for (int o = 16; o > 0; o >>= 1) wsv += __shfl_down_sync(0xffffffffu, wsv, o);
    if (lane == 0) wsum[wrp] = wsv;
    __syncthreads();

    if (tid == 0) {
        unsigned cum = 0; int w = 0;
        for (; w < 32; w++) { if (cum + wsum[w] > rank) break; cum += wsum[w]; }
        s_warp = w; s_base = cum;
    }
    __syncthreads();
    if (tid == s_warp * 32) {
        unsigned cum = s_base; int t = s_warp * 32;
        for (;; t++) { if (cum + part[t] > rank) break; cum += part[t]; }
        s_thread = t; s_base2 = cum;
    }
    __syncthreads();
    if (tid == s_thread) {
        unsigned cum = s_base2; int bin = tid * 64;
        for (;; bin++) { if (cum + bins[bin] > rank) break; cum += bins[bin]; }
        if (phase == 0) { g_hi16[b] = (unsigned)bin; g_selrank[b] = (int)(rank - cum); }
        else g_thrE[b] = (g_hi16[b] << 16) | (unsigned)bin;
    }
    __syncthreads();
    if (phase == 0) {
#pragma unroll 8
        for (int t = 0; t < 64; t++) bins[tid * 64 + t] = 0u;
    }
}

// ---------------- threshold + exp + partial sum ----------------
__global__ void thresh_kernel()
{
    int b = blockIdx.y, blk = blockIdx.x, tid = threadIdx.x;
    const float* sm = g_sc + (long)b * NN2;
    float* adj = g_adj + (long)b * NN2;
    float mx = dec_f(g_mxu[b]);
    unsigned thr = g_thrE[b];
    float s = 0.f;
    for (int i = blk * 256 + tid; i < NN2; i += 64 * 256) {
        float v = sm[i];
        unsigned e = enc_f(v);
        float keep = (e >= thr) ? expf(v - mx) : 0.f;
        adj[i] = keep;
        s += keep;
    }
    __shared__ float sh[256];
    sh[tid] = s; __syncthreads();
    for (int q = 128; q > 0; q >>= 1) { if (tid < q) sh[tid] += sh[tid + q]; __syncthreads(); }
    if (tid == 0) g_part[b * 64 + blk] = sh[0];
}
__global__ void inv_kernel()
{
    __shared__ float sh[64];
    int b = blockIdx.x, tid = threadIdx.x; // 64 threads
    sh[tid] = g_part[b * 64 + tid];
    __syncthreads();
    for (int q = 32; q > 0; q >>= 1) { if (tid < q) sh[tid] += sh[tid + q]; __syncthreads(); }
    if (tid == 0) g_inv[b] = 1.0f / sh[0];
}

// ---------------- batchnorm + relu ----------------
__global__ void bn_relu_kernel(float* __restrict__ h,
                               const float* __restrict__ ga,
                               const float* __restrict__ be, int C)
{
    __shared__ float sh[8][32], sh2[8][32];
    int c = blockIdx.x * 32 + threadIdx.x;
    int ry = threadIdx.y;
    float s = 0.f, s2 = 0.f;
    for (int r = ry; r < BN_M; r += 8) {
        float v = h[(long)r * C + c];
        s += v; s2 += v * v;
    }
    sh[ry][threadIdx.x] = s; sh2[ry][threadIdx.x] = s2;
    __syncthreads();
    if (ry == 0) {
        for (int r = 1; r < 8; r++) { s += sh[r][threadIdx.x]; s2 += sh2[r][threadIdx.x]; }
        float m = s / (float)BN_M;
        float v = s2 / (float)BN_M - m * m;
        sh[0][threadIdx.x] = m;
        sh2[0][threadIdx.x] = rsqrtf(v + 1e-5f);
    }
    __syncthreads();
    float m = sh[0][threadIdx.x], inv = sh2[0][threadIdx.x];
    float gg = ga[c], bb = be[c];
    for (int r = ry; r < BN_M; r += 8) {
        float v = h[(long)r * C + c];
        h[(long)r * C + c] = fmaxf((v - m) * inv * gg + bb, 0.f);
    }
}

// ---------------- mean pool + classifier ----------------
__global__ void head_kernel(const float* __restrict__ cls_w,
                            const float* __restrict__ cls_b,
                            float* __restrict__ out)
{
    __shared__ float acc4[4][OUTF];
    __shared__ float feat[OUTF];
    int b = blockIdx.x, tid = threadIdx.x; // 512 threads
    int r0 = tid >> 7, f = tid & 127;
    float s = 0.f;
    for (int r = r0; r < NN_NODES; r += 4)
        s += g_h2b[((long)b * NN_NODES + r) * OUTF + f];
    acc4[r0][f] = s;
    __syncthreads();
    if (tid < OUTF)
        feat[tid] = (acc4[0][tid] + acc4[1][tid] + acc4[2][tid] + acc4[3][tid]) / (float)NN_NODES;
    __syncthreads();
    if (tid < NCLS) {
        float acc = cls_b[tid];
        for (int ff = 0; ff < OUTF; ff++) acc += feat[ff] * cls_w[tid * OUTF + ff];
        out[b * NCLS + tid] = acc;
    }
}

// ---------------- launcher ----------------
extern "C" void kernel_launch(void* const* d_in, const int* in_sizes, int n_in,
                              void* d_out, int out_size)
{
    const float* x     = (const float*)d_in[0];
    const float* Wg    = (const float*)d_in[1];
    const float* attn  = (const float*)d_in[2];
    const float* W1    = (const float*)d_in[3];
    const float* b1    = (const float*)d_in[4];
    const float* w2    = (const float*)d_in[5];
    const float* b2    = (const float*)d_in[6];
    const float* gc1_w = (const float*)d_in[7];
    const float* gc1_b = (const float*)d_in[8];
    const float* bn1_g = (const float*)d_in[9];
    const float* bn1_b = (const float*)d_in[10];
    const float* gc2_w = (const float*)d_in[11];
    const float* gc2_b = (const float*)d_in[12];
    const float* bn2_g = (const float*)d_in[13];
    const float* bn2_b = (const float*)d_in[14];
    const float* cls_w = (const float*)d_in[15];
    const float* cls_b = (const float*)d_in[16];
    float* out = (float*)d_out;

    float *hp, *nf, *pij, *adj, *h1, *h1b, *h2, *h2b, *ginv;
    cudaGetSymbolAddress((void**)&hp,  g_hp);
    cudaGetSymbolAddress((void**)&nf,  g_nf);
    cudaGetSymbolAddress((void**)&pij, g_pij);
    cudaGetSymbolAddress((void**)&adj, g_adj);
    cudaGetSymbolAddress((void**)&h1,  g_h1);
    cudaGetSymbolAddress((void**)&h1b, g_h1b);
    cudaGetSymbolAddress((void**)&h2,  g_h2);
    cudaGetSymbolAddress((void**)&h2b, g_h2b);
    cudaGetSymbolAddress((void**)&ginv, g_inv);

    init_kernel<<<128, 1024>>>();

    // 1) hp = x @ Wg^T
    mma_gemm<true, false, false><<<dim3(16, 16, 1), 128>>>(
        x, FDIM, 0, Wg, FDIM, 0, nullptr, nullptr, hp, FDIM, 0, FDIM);

    // 2) s_i, s_j
    sij_kernel<<<(BB * HEADS * NN_NODES * 32 + 255) / 256, 256>>>(attn);

    // 3) attention softmax + aggregate
    attn_kernel<<<dim3(NN_NODES / 16, BB * HEADS), 256>>>();

    // 4) pi/pj fused (grid.z picks W1 half and output half)
    mma_gemm<true, false, false><<<dim3(AH / 64, 16, 2), 128>>>(
        nf, FDIM, 0, W1, 2 * FDIM, FDIM, nullptr, nullptr,
        pij, AH, (long)PJOFF, FDIM);

    // 5) edge scores + global max
    edge_kernel<<<dim3(NN_NODES / 16, NN_NODES / 16, BB), 256>>>(b1, w2, b2);

    // 6) exact k-th order statistic on raw scores (2-level 16-bit radix)
    histA_kernel<<<dim3(32, BB), 256>>>();
    pick_kernel<<<BB, 1024>>>(0);
    histB_kernel<<<dim3(32, BB), 256>>>();
    pick_kernel<<<BB, 1024>>>(1);

    // 7) threshold + exp + sum -> 1/denom
    thresh_kernel<<<dim3(64, BB), 256>>>();
    inv_kernel<<<BB, 64>>>();

    // 8) h1 = (adjU @ nf) * inv[b]
    mma_gemm<false, false, true><<<dim3(FDIM / 64, NN_NODES / 64, BB), 128>>>(
        adj, NN_NODES, (long)NN2, nf, FDIM, (long)NN_NODES * FDIM, nullptr, ginv,
        h1, FDIM, (long)NN_NODES * FDIM, NN_NODES);

    // 9) h1b = h1 @ gc1_w^T + gc1_b
    mma_gemm<true, true, false><<<dim3(HID / 64, 16, 1), 128>>>(
        h1, FDIM, 0, gc1_w, FDIM, 0, gc1_b, nullptr, h1b, HID, 0, FDIM);

    // 10) bn1 + relu
    bn_relu_kernel<<<HID / 32, dim3(32, 8)>>>(h1b, bn1_g, bn1_b, HID);

    // 11) h2 = (adjU @ h1b) * inv[b]
    mma_gemm<false, false, true><<<dim3(HID / 64, NN_NODES / 64, BB), 128>>>(
        adj, NN_NODES, (long)NN2, h1b, HID, (long)NN_NODES * HID, nullptr, ginv,
        h2, HID, (long)NN_NODES * HID, NN_NODES);

    // 12) h2b = h2 @ gc2_w^T + gc2_b
    mma_gemm<true, true, false><<<dim3(OUTF / 64, 16, 1), 128>>>(
        h2, HID, 0, gc2_w, HID, 0, gc2_b, nullptr, h2b, OUTF, 0, HID);

    // 13) bn2 + relu
    bn_relu_kernel<<<OUTF / 32, dim3(32, 8)>>>(h2b, bn2_g, bn2_b, OUTF);

    // 14) mean pool + classifier
    head_kernel<<<BB, 512>>>(cls_w, cls_b, out);
}

// round 7
// speedup vs baseline: 1.2961x; 1.2961x over previous
#include <cuda_runtime.h>
#include <cuda_bf16.h>
#include <math.h>

// ---------------- problem constants ----------------
#define BB 2
#define NN_NODES 512
#define FDIM 1024
#define HEADS 4
#define DH 256
#define AH 256
#define HID 512
#define OUTF 128
#define NCLS 10
#define NN2 (NN_NODES*NN_NODES)          // 262144
#define KSEL 209715                       // int(0.8 * N*N)
#define THR_IDX (NN2 - KSEL)              // 52429 (0-based ascending rank)
#define BN_M (BB*NN_NODES)
#define PJOFF (BB*NN_NODES*AH)

// ---------------- device scratch ----------------
__device__ float g_hp [BB*NN_NODES*FDIM];
__device__ float g_nf [BB*NN_NODES*FDIM];
__device__ float g_alpha[BB*HEADS*NN2];       // attention weights 8MB
__device__ float g_si [BB*HEADS*NN_NODES];
__device__ float g_sj [BB*HEADS*NN_NODES];
__device__ float g_pij[2*BB*NN_NODES*AH];
__device__ float g_sc [BB*NN2];               // raw scores (already /TEMP)
__device__ float g_adj[BB*NN2];               // kept exp values (unnormalized)
__device__ float g_h1 [BB*NN_NODES*FDIM];
__device__ float g_h1b[BB*NN_NODES*HID];
__device__ float g_h2 [BB*NN_NODES*HID];
__device__ float g_h2b[BB*NN_NODES*OUTF];
__device__ float g_part[BB*64];
__device__ float g_inv[BB];
__device__ unsigned g_mxu[BB];
__device__ unsigned g_sjmx[BB*HEADS];
__device__ unsigned g_h16[BB][65536];
__device__ unsigned g_hi16[BB];
__device__ int g_selrank[BB];
__device__ unsigned g_thrE[BB];

// ---------------- helpers ----------------
__device__ __forceinline__ float f2tf32f(float x) {
    unsigned r;
    asm("cvt.rna.tf32.f32 %0, %1;" : "=r"(r) : "f"(x));
    return __uint_as_float(r);
}
__device__ __forceinline__ unsigned enc_f(float f) {
    unsigned u = __float_as_uint(f);
    return (u & 0x80000000u) ? ~u : (u | 0x80000000u);
}
__device__ __forceinline__ float dec_f(unsigned e) {
    unsigned u = (e & 0x80000000u) ? (e ^ 0x80000000u) : ~e;
    return __uint_as_float(u);
}

// ---------------- 3xTF32 tensor-core GEMM (double-buffered fp32 smem) ----------------
// C[m,n] = sum_k A[m,k] * (TRANSB ? B[n,k] : B[k,n])  (+bias[n]) (*scale[z1])
// z-offsets: z1 = bz/zdiv, z2 = bz%zdiv; base += z1*s + z2*s2.
// 128 threads, tile 64x64, K-tile 32. hi/lo tf32 split done in registers.
#define APITCH 36
#define BPITCH 68
template<bool TRANSB, bool BIAS, bool SCALE>
__global__ void __launch_bounds__(128) mma_gemm(
    const float* __restrict__ A, int lda, long sA, long sA2,
    const float* __restrict__ Bm, int ldb, long sB, long sB2,
    const float* __restrict__ bias, const float* __restrict__ scale,
    float* __restrict__ C, int ldc, long sC, long sC2,
    int K, int zdiv)
{
    __shared__ float As[2][64 * APITCH];
    __shared__ float Bs[2][32 * BPITCH];

    const int bz = blockIdx.z;
    const int z1 = bz / zdiv, z2 = bz % zdiv;
    A  += z1 * sA + z2 * sA2;
    Bm += z1 * sB + z2 * sB2;
    C  += z1 * sC + z2 * sC2;
    const int m0 = blockIdx.y * 64;
    const int n0 = blockIdx.x * 64;
    const int tid = threadIdx.x;
    const int lane = tid & 31;
    const int wid  = tid >> 5;
    const int wm = wid >> 1, wn = wid & 1;
    const int g  = lane >> 2;
    const int tg = lane & 3;

    const int a_mr = tid >> 3;
    const int a_k4 = tid & 7;
    const int bt_nr = tid >> 3;
    const int bt_k4 = tid & 7;
    const int bn_kr = tid >> 4;
    const int bn_n4 = tid & 15;

    float acc[2][4][4];
#pragma unroll
    for (int im = 0; im < 2; im++)
#pragma unroll
        for (int in = 0; in < 4; in++)
#pragma unroll
            for (int q = 0; q < 4; q++) acc[im][in][q] = 0.f;

    const int niter = K >> 5;

#define MMA_OP(d, a0,a1,a2,a3, b0,b1)                                        \
    asm volatile("mma.sync.aligned.m16n8k8.row.col.f32.tf32.tf32.f32 "       \
                 "{%0,%1,%2,%3}, {%4,%5,%6,%7}, {%8,%9}, {%0,%1,%2,%3};"     \
                 : "+f"(d[0]), "+f"(d[1]), "+f"(d[2]), "+f"(d[3])            \
                 : "r"(a0), "r"(a1), "r"(a2), "r"(a3), "r"(b0), "r"(b1))

    // ---- prologue: tile 0 straight to smem ----
    {
#pragma unroll
        for (int i = 0; i < 4; i++) {
            int m = a_mr + 16 * i;
            float4 v = *(const float4*)&A[(long)(m0 + m) * lda + a_k4 * 4];
            *(float4*)&As[0][m * APITCH + a_k4 * 4] = v;
        }
        if (TRANSB) {
#pragma unroll
            for (int i = 0; i < 4; i++) {
                int n = bt_nr + 16 * i;
                float4 v = *(const float4*)&Bm[(long)(n0 + n) * ldb + bt_k4 * 4];
                Bs[0][(bt_k4 * 4 + 0) * BPITCH + n] = v.x;
                Bs[0][(bt_k4 * 4 + 1) * BPITCH + n] = v.y;
                Bs[0][(bt_k4 * 4 + 2) * BPITCH + n] = v.z;
                Bs[0][(bt_k4 * 4 + 3) * BPITCH + n] = v.w;
            }
        } else {
#pragma unroll
            for (int i = 0; i < 4; i++) {
                int kk = bn_kr + 8 * i;
                float4 v = *(const float4*)&Bm[(long)kk * ldb + n0 + bn_n4 * 4];
                *(float4*)&Bs[0][kk * BPITCH + bn_n4 * 4] = v;
            }
        }
    }
    __syncthreads();

    int buf = 0;
    for (int it = 0; it < niter; it++) {
        float4 ra[4], rb[4];
        const bool more = (it + 1 < niter);
        if (more) {
            const int k0 = (it + 1) << 5;
#pragma unroll
            for (int i = 0; i < 4; i++) {
                int m = a_mr + 16 * i;
                ra[i] = *(const float4*)&A[(long)(m0 + m) * lda + k0 + a_k4 * 4];
            }
            if (TRANSB) {
#pragma unroll
                for (int i = 0; i < 4; i++) {
                    int n = bt_nr + 16 * i;
                    rb[i] = *(const float4*)&Bm[(long)(n0 + n) * ldb + k0 + bt_k4 * 4];
                }
            } else {
#pragma unroll
                for (int i = 0; i < 4; i++) {
                    int kk = bn_kr + 8 * i;
                    rb[i] = *(const float4*)&Bm[(long)(k0 + kk) * ldb + n0 + bn_n4 * 4];
                }
            }
        }

        // ---- compute on buf, hi/lo split in registers ----
#pragma unroll
        for (int ks = 0; ks < 4; ks++) {
            unsigned ah[2][4], al[2][4];
#pragma unroll
            for (int im = 0; im < 2; im++) {
                int mb = wm * 32 + im * 16;
                float v0 = As[buf][(mb + g) * APITCH + ks * 8 + tg];
                float v1 = As[buf][(mb + 8 + g) * APITCH + ks * 8 + tg];
                float v2 = As[buf][(mb + g) * APITCH + ks * 8 + 4 + tg];
                float v3 = As[buf][(mb + 8 + g) * APITCH + ks * 8 + 4 + tg];
                float h0 = f2tf32f(v0), h1v = f2tf32f(v1), h2v = f2tf32f(v2), h3v = f2tf32f(v3);
                ah[im][0] = __float_as_uint(h0);  al[im][0] = __float_as_uint(v0 - h0);
                ah[im][1] = __float_as_uint(h1v); al[im][1] = __float_as_uint(v1 - h1v);
                ah[im][2] = __float_as_uint(h2v); al[im][2] = __float_as_uint(v2 - h2v);
                ah[im][3] = __float_as_uint(h3v); al[im][3] = __float_as_uint(v3 - h3v);
            }
            unsigned bh[4][2], bl[4][2];
#pragma unroll
            for (int in = 0; in < 4; in++) {
                int nb = wn * 32 + in * 8;
                float v0 = Bs[buf][(ks * 8 + tg) * BPITCH + nb + g];
                float v1 = Bs[buf][(ks * 8 + 4 + tg) * BPITCH + nb + g];
                float h0 = f2tf32f(v0), h1v = f2tf32f(v1);
                bh[in][0] = __float_as_uint(h0);  bl[in][0] = __float_as_uint(v0 - h0);
                bh[in][1] = __float_as_uint(h1v); bl[in][1] = __float_as_uint(v1 - h1v);
            }
#pragma unroll
            for (int im = 0; im < 2; im++)
#pragma unroll
                for (int in = 0; in < 4; in++) {
                    MMA_OP(acc[im][in], al[im][0], al[im][1], al[im][2], al[im][3],
                           bh[in][0], bh[in][1]);
                    MMA_OP(acc[im][in], ah[im][0], ah[im][1], ah[im][2], ah[im][3],
                           bl[in][0], bl[in][1]);
                    MMA_OP(acc[im][in], ah[im][0], ah[im][1], ah[im][2], ah[im][3],
                           bh[in][0], bh[in][1]);
                }
        }

        if (more) {
            int nb = buf ^ 1;
#pragma unroll
            for (int i = 0; i < 4; i++) {
                int m = a_mr + 16 * i;
                *(float4*)&As[nb][m * APITCH + a_k4 * 4] = ra[i];
            }
            if (TRANSB) {
#pragma unroll
                for (int i = 0; i < 4; i++) {
                    int n = bt_nr + 16 * i;
                    Bs[nb][(bt_k4 * 4 + 0) * BPITCH + n] = rb[i].x;
                    Bs[nb][(bt_k4 * 4 + 1) * BPITCH + n] = rb[i].y;
                    Bs[nb][(bt_k4 * 4 + 2) * BPITCH + n] = rb[i].z;
                    Bs[nb][(bt_k4 * 4 + 3) * BPITCH + n] = rb[i].w;
                }
            } else {
#pragma unroll
                for (int i = 0; i < 4; i++) {
                    int kk = bn_kr + 8 * i;
                    *(float4*)&Bs[nb][kk * BPITCH + bn_n4 * 4] = rb[i];
                }
            }
        }
        __syncthreads();
        buf ^= 1;
    }

    float scv = SCALE ? scale[z1] : 1.f;
#pragma unroll
    for (int im = 0; im < 2; im++) {
        int r0 = m0 + wm * 32 + im * 16 + g;
        int r1 = r0 + 8;
#pragma unroll
        for (int in = 0; in < 4; in++) {
            int c = n0 + wn * 32 + in * 8 + 2 * tg;
            float b0 = 0.f, b1v = 0.f;
            if (BIAS) { b0 = bias[c]; b1v = bias[c + 1]; }
            float2 v0, v1;
            if (SCALE) {
                v0 = make_float2(acc[im][in][0] * scv, acc[im][in][1] * scv);
                v1 = make_float2(acc[im][in][2] * scv, acc[im][in][3] * scv);
            } else {
                v0 = make_float2(acc[im][in][0] + b0, acc[im][in][1] + b1v);
                v1 = make_float2(acc[im][in][2] + b0, acc[im][in][3] + b1v);
            }
            *(float2*)&C[(long)r0 * ldc + c] = v0;
            *(float2*)&C[(long)r1 * ldc + c] = v1;
        }
    }
#undef MMA_OP
}

// ---------------- init (clear histograms + maxes) ----------------
__global__ void init_kernel()
{
    int idx = blockIdx.x * 1024 + threadIdx.x;   // 128 x 1024 = 131072
    int b = idx >> 16, bin = idx & 65535;
    g_h16[b][bin] = 0u;
    if (idx < BB) g_mxu[idx] = 0u;
    if (idx < BB * HEADS) g_sjmx[idx] = 0u;
}

// ---------------- s_i, s_j + per-(b,h) max of s_j ----------------
__global__ void sij_kernel(const float* __restrict__ attn)
{
    int gw = (blockIdx.x * blockDim.x + threadIdx.x) >> 5;
    int lane = threadIdx.x & 31;
    if (gw >= BB * HEADS * NN_NODES) return;
    int b = gw / (HEADS * NN_NODES);
    int r = gw % (HEADS * NN_NODES);
    int h = r / NN_NODES;
    int n = r % NN_NODES;
    const float* hp = g_hp + ((long)(b * NN_NODES + n)) * FDIM + h * DH;
    const float* ai = attn + h * 2 * DH;
    float si = 0.f, sj = 0.f;
#pragma unroll
    for (int d = lane; d < DH; d += 32) {
        float v = hp[d];
        si += v * ai[d];
        sj += v * ai[DH + d];
    }
#pragma unroll
    for (int o = 16; o > 0; o >>= 1) {
        si += __shfl_down_sync(0xffffffffu, si, o);
        sj += __shfl_down_sync(0xffffffffu, sj, o);
    }
    if (lane == 0) {
        g_si[gw] = si;
        g_sj[gw] = sj;
        atomicMax(&g_sjmx[b * HEADS + h], enc_f(sj));
    }
}

// ---------------- attention softmax rows -> g_alpha ----------------
// grid (N/8, B*H), block 256 = 8 warps, warp per row i.
__global__ void alpha_kernel()
{
    __shared__ float sj[NN_NODES];
    int bh = blockIdx.y;
    int tid = threadIdx.x;
    for (int j = tid; j < NN_NODES; j += 256) sj[j] = g_sj[bh * NN_NODES + j];
    __syncthreads();

    int wrp = tid >> 5, lane = tid & 31;
    int i = blockIdx.x * 8 + wrp;
    float si = g_si[bh * NN_NODES + i];
    float sjmax = dec_f(g_sjmx[bh]);
    float M = si + sjmax;
    M = (M >= 0.f) ? M : 0.2f * M;   // leaky monotone -> row max
    float p[16];
    float sum = 0.f;
#pragma unroll
    for (int t = 0; t < 16; t++) {
        float e = si + sj[lane + 32 * t];
        e = (e >= 0.f) ? e : 0.2f * e;
        p[t] = expf(e - M);
        sum += p[t];
    }
#pragma unroll
    for (int o = 16; o > 0; o >>= 1) sum += __shfl_xor_sync(0xffffffffu, sum, o);
    float inv = 1.0f / sum;
    float* row = g_alpha + (long)bh * NN2 + (long)i * NN_NODES;
#pragma unroll
    for (int t = 0; t < 16; t++) row[lane + 32 * t] = p[t] * inv;
}

// ---------------- edge MLP scores + global max ----------------
__global__ void edge_kernel(const float* __restrict__ b1,
                            const float* __restrict__ w2,
                            const float* __restrict__ b2p)
{
    __shared__ float spi[16][260];
    __shared__ float spj[16][260];
    __shared__ float sw2[AH];
    __shared__ float red[256];
    int b = blockIdx.z;
    int i0 = blockIdx.y * 16, j0 = blockIdx.x * 16;
    int tid = threadIdx.x;

    float b1v = b1[tid];
    sw2[tid] = w2[tid];
#pragma unroll
    for (int l = 0; l < 16; l++) {
        spi[l][tid] = g_pij[((long)(b * NN_NODES) + i0 + l) * AH + tid] + b1v;
        spj[l][tid] = g_pij[PJOFF + ((long)(b * NN_NODES) + j0 + l) * AH + tid];
    }
    __syncthreads();
    int ti = tid >> 4, tj = tid & 15;
    float acc = 0.f;
#pragma unroll
    for (int a = 0; a < AH; a += 4) {
        float4 p4 = *(const float4*)&spi[ti][a];
        float4 q4 = *(const float4*)&spj[tj][a];
        float4 w4 = *(const float4*)&sw2[a];
        acc += fmaxf(p4.x + q4.x, 0.f) * w4.x;
        acc += fmaxf(p4.y + q4.y, 0.f) * w4.y;
        acc += fmaxf(p4.z + q4.z, 0.f) * w4.z;
        acc += fmaxf(p4.w + q4.w, 0.f) * w4.w;
    }
    float sc = (acc + b2p[0]) * 2.0f;   // /TEMP
    g_sc[(long)b * NN2 + (long)(i0 + ti) * NN_NODES + (j0 + tj)] = sc;

    red[tid] = sc;
    __syncthreads();
    for (int s = 128; s > 0; s >>= 1) {
        if (tid < s) red[tid] = fmaxf(red[tid], red[tid + s]);
        __syncthreads();
    }
    if (tid == 0) atomicMax(&g_mxu[b], enc_f(red[0]));
}

// ---------------- 2-level radix select on encoded scores ----------------
__global__ void histA_kernel()
{
    int b = blockIdx.y, blk = blockIdx.x, tid = threadIdx.x;
    const float* sm = g_sc + (long)b * NN2;
    for (int i = blk * 256 + tid; i < NN2; i += 32 * 256) {
        unsigned e = enc_f(sm[i]);
        atomicAdd(&g_h16[b][e >> 16], 1u);
    }
}
__global__ void histB_kernel()
{
    int b = blockIdx.y, blk = blockIdx.x, tid = threadIdx.x;
    unsigned hi = g_hi16[b];
    const float* sm = g_sc + (long)b * NN2;
    for (int i = blk * 256 + tid; i < NN2; i += 32 * 256) {
        unsigned e = enc_f(sm[i]);
        if ((e >> 16) == hi) atomicAdd(&g_h16[b][e & 0xFFFFu], 1u);
    }
}
__global__ void pick_kernel(int phase)
{
    __shared__ unsigned part[1024];
    __shared__ unsigned wsum[32];
    __shared__ int s_warp, s_thread;
    __shared__ unsigned s_base, s_base2;
    int b = blockIdx.x, tid = threadIdx.x, lane = tid & 31, wrp = tid >> 5;
    unsigned* bins = g_h16[b];
    unsigned rank = (phase == 0) ? (unsigned)THR_IDX : (unsigned)g_selrank[b];

    unsigned s = 0;
#pragma unroll 8
    for (int t = 0; t < 64; t++) s += bins[tid * 64 + t];
    part[tid] = s;
    unsigned wsv = s;
#pragma unroll
    for (int o = 16; o > 0; o >>= 1) wsv += __shfl_down_sync(0xffffffffu, wsv, o);
    if (lane == 0) wsum[wrp] = wsv;
    __syncthreads();

    if (tid == 0) {
        unsigned cum = 0; int w = 0;
        for (; w < 32; w++) { if (cum + wsum[w] > rank) break; cum += wsum[w]; }
        s_warp = w; s_base = cum;
    }
    __syncthreads();
    if (tid == s_warp * 32) {
        unsigned cum = s_base; int t = s_warp * 32;
        for (;; t++) { if (cum + part[t] > rank) break; cum += part[t]; }
        s_thread = t; s_base2 = cum;
    }
    __syncthreads();
    if (tid == s_thread) {
        unsigned cum = s_base2; int bin = tid * 64;
        for (;; bin++) { if (cum + bins[bin] > rank) break; cum += bins[bin]; }
        if (phase == 0) { g_hi16[b] = (unsigned)bin; g_selrank[b] = (int)(rank - cum); }
        else g_thrE[b] = (g_hi16[b] << 16) | (unsigned)bin;
    }
    __syncthreads();
    if (phase == 0) {
#pragma unroll 8
        for (int t = 0; t < 64; t++) bins[tid * 64 + t] = 0u;
    }
}

// ---------------- threshold + exp + partial sum ----------------
__global__ void thresh_kernel()
{
    int b = blockIdx.y, blk = blockIdx.x, tid = threadIdx.x;
    const float* sm = g_sc + (long)b * NN2;
    float* adj = g_adj + (long)b * NN2;
    float mx = dec_f(g_mxu[b]);
    unsigned thr = g_thrE[b];
    float s = 0.f;
    for (int i = blk * 256 + tid; i < NN2; i += 64 * 256) {
        float v = sm[i];
        unsigned e = enc_f(v);
        float keep = (e >= thr) ? expf(v - mx) : 0.f;
        adj[i] = keep;
        s += keep;
    }
    __shared__ float sh[256];
    sh[tid] = s; __syncthreads();
    for (int q = 128; q > 0; q >>= 1) { if (tid < q) sh[tid] += sh[tid + q]; __syncthreads(); }
    if (tid == 0) g_part[b * 64 + blk] = sh[0];
}
__global__ void inv_kernel()
{
    __shared__ float sh[64];
    int b = blockIdx.x, tid = threadIdx.x; // 64 threads
    sh[tid] = g_part[b * 64 + tid];
    __syncthreads();
    for (int q = 32; q > 0; q >>= 1) { if (tid < q) sh[tid] += sh[tid + q]; __syncthreads(); }
    if (tid == 0) g_inv[b] = 1.0f / sh[0];
}

// ---------------- batchnorm + relu ----------------
__global__ void bn_relu_kernel(float* __restrict__ h,
                               const float* __restrict__ ga,
                               const float* __restrict__ be, int C)
{
    __shared__ float sh[8][32], sh2[8][32];
    int c = blockIdx.x * 32 + threadIdx.x;
    int ry = threadIdx.y;
    float s = 0.f, s2 = 0.f;
    for (int r = ry; r < BN_M; r += 8) {
        float v = h[(long)r * C + c];
        s += v; s2 += v * v;
    }
    sh[ry][threadIdx.x] = s; sh2[ry][threadIdx.x] = s2;
    __syncthreads();
    if (ry == 0) {
        for (int r = 1; r < 8; r++) { s += sh[r][threadIdx.x]; s2 += sh2[r][threadIdx.x]; }
        float m = s / (float)BN_M;
        float v = s2 / (float)BN_M - m * m;
        sh[0][threadIdx.x] = m;
        sh2[0][threadIdx.x] = rsqrtf(v + 1e-5f);
    }
    __syncthreads();
    float m = sh[0][threadIdx.x], inv = sh2[0][threadIdx.x];
    float gg = ga[c], bb = be[c];
    for (int r = ry; r < BN_M; r += 8) {
        float v = h[(long)r * C + c];
        h[(long)r * C + c] = fmaxf((v - m) * inv * gg + bb, 0.f);
    }
}

// ---------------- mean pool + classifier ----------------
__global__ void head_kernel(const float* __restrict__ cls_w,
                            const float* __restrict__ cls_b,
                            float* __restrict__ out)
{
    __shared__ float acc4[4][OUTF];
    __shared__ float feat[OUTF];
    int b = blockIdx.x, tid = threadIdx.x; // 512 threads
    int r0 = tid >> 7, f = tid & 127;
    float s = 0.f;
    for (int r = r0; r < NN_NODES; r += 4)
        s += g_h2b[((long)b * NN_NODES + r) * OUTF + f];
    acc4[r0][f] = s;
    __syncthreads();
    if (tid < OUTF)
        feat[tid] = (acc4[0][tid] + acc4[1][tid] + acc4[2][tid] + acc4[3][tid]) / (float)NN_NODES;
    __syncthreads();
    if (tid < NCLS) {
        float acc = cls_b[tid];
        for (int ff = 0; ff < OUTF; ff++) acc += feat[ff] * cls_w[tid * OUTF + ff];
        out[b * NCLS + tid] = acc;
    }
}

// ---------------- launcher ----------------
extern "C" void kernel_launch(void* const* d_in, const int* in_sizes, int n_in,
                              void* d_out, int out_size)
{
    const float* x     = (const float*)d_in[0];
    const float* Wg    = (const float*)d_in[1];
    const float* attn  = (const float*)d_in[2];
    const float* W1    = (const float*)d_in[3];
    const float* b1    = (const float*)d_in[4];
    const float* w2    = (const float*)d_in[5];
    const float* b2    = (const float*)d_in[6];
    const float* gc1_w = (const float*)d_in[7];
    const float* gc1_b = (const float*)d_in[8];
    const float* bn1_g = (const float*)d_in[9];
    const float* bn1_b = (const float*)d_in[10];
    const float* gc2_w = (const float*)d_in[11];
    const float* gc2_b = (const float*)d_in[12];
    const float* bn2_g = (const float*)d_in[13];
    const float* bn2_b = (const float*)d_in[14];
    const float* cls_w = (const float*)d_in[15];
    const float* cls_b = (const float*)d_in[16];
    float* out = (float*)d_out;

    float *hp, *nf, *alpha, *pij, *adj, *h1, *h1b, *h2, *h2b, *ginv;
    cudaGetSymbolAddress((void**)&hp,  g_hp);
    cudaGetSymbolAddress((void**)&nf,  g_nf);
    cudaGetSymbolAddress((void**)&alpha, g_alpha);
    cudaGetSymbolAddress((void**)&pij, g_pij);
    cudaGetSymbolAddress((void**)&adj, g_adj);
    cudaGetSymbolAddress((void**)&h1,  g_h1);
    cudaGetSymbolAddress((void**)&h1b, g_h1b);
    cudaGetSymbolAddress((void**)&h2,  g_h2);
    cudaGetSymbolAddress((void**)&h2b, g_h2b);
    cudaGetSymbolAddress((void**)&ginv, g_inv);

    init_kernel<<<128, 1024>>>();

    // 1) hp = x @ Wg^T
    mma_gemm<true, false, false><<<dim3(16, 16, 1), 128>>>(
        x, FDIM, 0, 0, Wg, FDIM, 0, 0, nullptr, nullptr, hp, FDIM, 0, 0, FDIM, 1);

    // 2) s_i, s_j + sjmax
    sij_kernel<<<(BB * HEADS * NN_NODES * 32 + 255) / 256, 256>>>(attn);

    // 3a) softmax rows -> alpha
    alpha_kernel<<<dim3(NN_NODES / 8, BB * HEADS), 256>>>();

    // 3b) nf[b,:,h*DH:(h+1)*DH] = alpha[bh] @ hp[b,:,h*DH:(h+1)*DH]
    mma_gemm<false, false, false><<<dim3(DH / 64, NN_NODES / 64, BB * HEADS), 128>>>(
        alpha, NN_NODES, (long)HEADS * NN2, (long)NN2,
        hp, FDIM, (long)NN_NODES * FDIM, (long)DH,
        nullptr, nullptr,
        nf, FDIM, (long)NN_NODES * FDIM, (long)DH, NN_NODES, HEADS);

    // 4) pi/pj fused (grid.z picks W1 half and output half)
    mma_gemm<true, false, false><<<dim3(AH / 64, 16, 2), 128>>>(
        nf, FDIM, 0, 0, W1, 2 * FDIM, FDIM, 0, nullptr, nullptr,
        pij, AH, (long)PJOFF, 0, FDIM, 1);

    // 5) edge scores + global max
    edge_kernel<<<dim3(NN_NODES / 16, NN_NODES / 16, BB), 256>>>(b1, w2, b2);

    // 6) exact k-th order statistic on raw scores (2-level 16-bit radix)
    histA_kernel<<<dim3(32, BB), 256>>>();
    pick_kernel<<<BB, 1024>>>(0);
    histB_kernel<<<dim3(32, BB), 256>>>();
    pick_kernel<<<BB, 1024>>>(1);

    // 7) threshold + exp + sum -> 1/denom
    thresh_kernel<<<dim3(64, BB), 256>>>();
    inv_kernel<<<BB, 64>>>();

    // 8) h1 = (adjU @ nf) * inv[b]
    mma_gemm<false, false, true><<<dim3(FDIM / 64, NN_NODES / 64, BB), 128>>>(
        adj, NN_NODES, (long)NN2, 0, nf, FDIM, (long)NN_NODES * FDIM, 0,
        nullptr, ginv, h1, FDIM, (long)NN_NODES * FDIM, 0, NN_NODES, 1);

    // 9) h1b = h1 @ gc1_w^T + gc1_b
    mma_gemm<true, true, false><<<dim3(HID / 64, 16, 1), 128>>>(
        h1, FDIM, 0, 0, gc1_w, FDIM, 0, 0, gc1_b, nullptr, h1b, HID, 0, 0, FDIM, 1);

    // 10) bn1 + relu
    bn_relu_kernel<<<HID / 32, dim3(32, 8)>>>(h1b, bn1_g, bn1_b, HID);

    // 11) h2 = (adjU @ h1b) * inv[b]
    mma_gemm<false, false, true><<<dim3(HID / 64, NN_NODES / 64, BB), 128>>>(
        adj, NN_NODES, (long)NN2, 0, h1b, HID, (long)NN_NODES * HID, 0,
        nullptr, ginv, h2, HID, (long)NN_NODES * HID, 0, NN_NODES, 1);

    // 12) h2b = h2 @ gc2_w^T + gc2_b
    mma_gemm<true, true, false><<<dim3(OUTF / 64, 16, 1), 128>>>(
        h2, HID, 0, 0, gc2_w, HID, 0, 0, gc2_b, nullptr, h2b, OUTF, 0, 0, HID, 1);

    // 13) bn2 + relu
    bn_relu_kernel<<<OUTF / 32, dim3(32, 8)>>>(h2b, bn2_g, bn2_b, OUTF);

    // 14) mean pool + classifier
    head_kernel<<<BB, 512>>>(cls_w, cls_b, out);
}

// round 9
// speedup vs baseline: 1.5585x; 1.2024x over previous
#include <cuda_runtime.h>
#include <cuda_bf16.h>
#include <math.h>

// ---------------- problem constants ----------------
#define BB 2
#define NN_NODES 512
#define FDIM 1024
#define HEADS 4
#define DH 256
#define AH 256
#define HID 512
#define OUTF 128
#define NCLS 10
#define NN2 (NN_NODES*NN_NODES)          // 262144
#define KSEL 209715                       // int(0.8 * N*N)
#define THR_IDX (NN2 - KSEL)              // 52429 (0-based ascending rank)
#define BN_M (BB*NN_NODES)
#define PJOFF (BB*NN_NODES*AH)

// ---------------- device scratch ----------------
__device__ float g_hp [BB*NN_NODES*FDIM];
__device__ float g_nf [BB*NN_NODES*FDIM];
__device__ float g_alpha[BB*HEADS*NN2];
__device__ float g_si [BB*HEADS*NN_NODES];
__device__ float g_sj [BB*HEADS*NN_NODES];
__device__ float g_pij[2*BB*NN_NODES*AH];
__device__ float g_sc [BB*NN2];
__device__ float g_adj[BB*NN2];
__device__ float g_h1 [BB*NN_NODES*FDIM];
__device__ float g_h1b[BB*NN_NODES*HID];
__device__ float g_h2 [BB*NN_NODES*HID];
__device__ float g_h2b[BB*NN_NODES*OUTF];
__device__ float g_part[BB*64];
__device__ float g_inv[BB];
__device__ unsigned g_mxu[BB];
__device__ unsigned g_sjmx[BB*HEADS];
__device__ unsigned g_h16[BB][65536];
__device__ unsigned g_hi16[BB];
__device__ int g_selrank[BB];
__device__ unsigned g_thrE[BB];

// ---------------- helpers ----------------
__device__ __forceinline__ unsigned enc_f(float f) {
    unsigned u = __float_as_uint(f);
    return (u & 0x80000000u) ? ~u : (u | 0x80000000u);
}
__device__ __forceinline__ float dec_f(unsigned e) {
    unsigned u = (e & 0x80000000u) ? (e ^ 0x80000000u) : ~e;
    return __uint_as_float(u);
}

// split a float4 into bf16 hi + bf16 lo residual, store as two bf16x2 each
__device__ __forceinline__ void split4(float4 v, __nv_bfloat16* H, __nv_bfloat16* L, int idx)
{
    __nv_bfloat162 h0 = __floats2bfloat162_rn(v.x, v.y);
    __nv_bfloat162 h1 = __floats2bfloat162_rn(v.z, v.w);
    float2 f0 = __bfloat1622float2(h0);
    float2 f1 = __bfloat1622float2(h1);
    __nv_bfloat162 l0 = __floats2bfloat162_rn(v.x - f0.x, v.y - f0.y);
    __nv_bfloat162 l1 = __floats2bfloat162_rn(v.z - f1.x, v.w - f1.y);
    *reinterpret_cast<__nv_bfloat162*>(H + idx)     = h0;
    *reinterpret_cast<__nv_bfloat162*>(H + idx + 2) = h1;
    *reinterpret_cast<__nv_bfloat162*>(L + idx)     = l0;
    *reinterpret_cast<__nv_bfloat162*>(L + idx + 2) = l1;
}

__device__ __forceinline__ void ldsm4(unsigned addr, unsigned& r0, unsigned& r1,
                                      unsigned& r2, unsigned& r3)
{
    asm volatile("ldmatrix.sync.aligned.m8n8.x4.shared.b16 {%0,%1,%2,%3}, [%4];"
                 : "=r"(r0), "=r"(r1), "=r"(r2), "=r"(r3) : "r"(addr));
}
__device__ __forceinline__ void ldsm4t(unsigned addr, unsigned& r0, unsigned& r1,
                                       unsigned& r2, unsigned& r3)
{
    asm volatile("ldmatrix.sync.aligned.m8n8.x4.trans.shared.b16 {%0,%1,%2,%3}, [%4];"
                 : "=r"(r0), "=r"(r1), "=r"(r2), "=r"(r3) : "r"(addr));
}

// ---------------- bf16 2-term split tensor-core GEMM ----------------
// C[m,n] = sum_k A[m,k] * (TRANSB ? B[n,k] : B[k,n])  (+bias[n]) (*scale[z1])
// 128 threads, tile 64x64, K-tile 32, double-buffered bf16 hi/lo smem.
#define AP  40   // [row][k] pitch in bf16 (A always; B when TRANSB)
#define BPN 72   // [k][n] pitch in bf16 (B when !TRANSB)
template<bool TRANSB, bool BIAS, bool SCALE>
__global__ void __launch_bounds__(128) mma_gemm(
    const float* __restrict__ A, int lda, long sA, long sA2,
    const float* __restrict__ Bm, int ldb, long sB, long sB2,
    const float* __restrict__ bias, const float* __restrict__ scale,
    float* __restrict__ C, int ldc, long sC, long sC2,
    int K, int zdiv)
{
    __shared__ __align__(16) __nv_bfloat16 Ahs[2][64 * AP];
    __shared__ __align__(16) __nv_bfloat16 Als[2][64 * AP];
    __shared__ __align__(16) __nv_bfloat16 Bhs[2][64 * AP];   // fits both layouts
    __shared__ __align__(16) __nv_bfloat16 Bls[2][64 * AP];

    const int bz = blockIdx.z;
    const int z1 = bz / zdiv, z2 = bz % zdiv;
    A  += z1 * sA + z2 * sA2;
    Bm += z1 * sB + z2 * sB2;
    C  += z1 * sC + z2 * sC2;
    const int m0 = blockIdx.y * 64;
    const int n0 = blockIdx.x * 64;
    const int tid = threadIdx.x;
    const int lane = tid & 31;
    const int wid  = tid >> 5;
    const int wm = wid >> 1, wn = wid & 1;
    const int g  = lane >> 2;
    const int tg = lane & 3;

    // staging indices
    const int a_mr = tid >> 3;      // 0..15 (+16i)
    const int a_k4 = tid & 7;       // float4 at k=4*a_k4
    const int bn_kr = tid >> 4;     // 0..7 (+8i) for !TRANSB
    const int bn_n4 = tid & 15;     // float4 at n=4*bn_n4

    // ldmatrix per-lane element offsets
    const int l7 = lane & 7;
    const int lb3 = (lane >> 3) & 1;
    const int lb4 = lane >> 4;
    const int offA  = (wm * 32 + l7 + 8 * lb3) * AP + 8 * lb4;          // +16*AP per im, +16 per ks
    const int offBT = (wn * 32 + l7 + 8 * lb4) * AP + 8 * lb3;          // +16*AP per q,  +16 per ks
    const int offBN = (l7 + 8 * lb3) * BPN + wn * 32 + 8 * lb4;         // +16 per q, +16*BPN per ks

    const unsigned baseAh = (unsigned)__cvta_generic_to_shared(&Ahs[0][0]);
    const unsigned baseAl = (unsigned)__cvta_generic_to_shared(&Als[0][0]);
    const unsigned baseBh = (unsigned)__cvta_generic_to_shared(&Bhs[0][0]);
    const unsigned baseBl = (unsigned)__cvta_generic_to_shared(&Bls[0][0]);
    const unsigned bufstep = 64 * AP * 2;  // bytes per buffer

    float acc[2][4][4];
#pragma unroll
    for (int im = 0; im < 2; im++)
#pragma unroll
        for (int in = 0; in < 4; in++)
#pragma unroll
            for (int q = 0; q < 4; q++) acc[im][in][q] = 0.f;

    const int niter = K >> 5;

#define MMAB(d, a, b0, b1)                                                    \
    asm volatile("mma.sync.aligned.m16n8k16.row.col.f32.bf16.bf16.f32 "       \
                 "{%0,%1,%2,%3}, {%4,%5,%6,%7}, {%8,%9}, {%0,%1,%2,%3};"      \
                 : "+f"(d[0]), "+f"(d[1]), "+f"(d[2]), "+f"(d[3])             \
                 : "r"(a[0]), "r"(a[1]), "r"(a[2]), "r"(a[3]), "r"(b0), "r"(b1))

    // ---- prologue: tile 0 ----
    {
#pragma unroll
        for (int i = 0; i < 4; i++) {
            int m = a_mr + 16 * i;
            float4 v = *(const float4*)&A[(long)(m0 + m) * lda + a_k4 * 4];
            split4(v, Ahs[0], Als[0], m * AP + a_k4 * 4);
        }
        if (TRANSB) {
#pragma unroll
            for (int i = 0; i < 4; i++) {
                int n = a_mr + 16 * i;
                float4 v = *(const float4*)&Bm[(long)(n0 + n) * ldb + a_k4 * 4];
                split4(v, Bhs[0], Bls[0], n * AP + a_k4 * 4);
            }
        } else {
#pragma unroll
            for (int i = 0; i < 4; i++) {
                int kk = bn_kr + 8 * i;
                float4 v = *(const float4*)&Bm[(long)kk * ldb + n0 + bn_n4 * 4];
                split4(v, Bhs[0], Bls[0], kk * BPN + bn_n4 * 4);
            }
        }
    }
    __syncthreads();

    int buf = 0;
    for (int it = 0; it < niter; it++) {
        float4 ra[4], rb[4];
        const bool more = (it + 1 < niter);
        if (more) {
            const int k0 = (it + 1) << 5;
#pragma unroll
            for (int i = 0; i < 4; i++) {
                int m = a_mr + 16 * i;
                ra[i] = *(const float4*)&A[(long)(m0 + m) * lda + k0 + a_k4 * 4];
            }
            if (TRANSB) {
#pragma unroll
                for (int i = 0; i < 4; i++) {
                    int n = a_mr + 16 * i;
                    rb[i] = *(const float4*)&Bm[(long)(n0 + n) * ldb + k0 + a_k4 * 4];
                }
            } else {
#pragma unroll
                for (int i = 0; i < 4; i++) {
                    int kk = bn_kr + 8 * i;
                    rb[i] = *(const float4*)&Bm[(long)(k0 + kk) * ldb + n0 + bn_n4 * 4];
                }
            }
        }

        // ---- compute on buf ----
        const unsigned aH = baseAh + buf * bufstep;
        const unsigned aL = baseAl + buf * bufstep;
        const unsigned bH = baseBh + buf * bufstep;
        const unsigned bL = baseBl + buf * bufstep;
#pragma unroll
        for (int ks = 0; ks < 2; ks++) {
            unsigned ah[2][4], al[2][4], bh[2][4], bl[2][4];
#pragma unroll
            for (int im = 0; im < 2; im++) {
                unsigned off = 2u * (offA + im * 16 * AP + ks * 16);
                ldsm4(aH + off, ah[im][0], ah[im][1], ah[im][2], ah[im][3]);
                ldsm4(aL + off, al[im][0], al[im][1], al[im][2], al[im][3]);
            }
#pragma unroll
            for (int q = 0; q < 2; q++) {
                if (TRANSB) {
                    unsigned off = 2u * (offBT + q * 16 * AP + ks * 16);
                    ldsm4(bH + off, bh[q][0], bh[q][1], bh[q][2], bh[q][3]);
                    ldsm4(bL + off, bl[q][0], bl[q][1], bl[q][2], bl[q][3]);
                } else {
                    unsigned off = 2u * (offBN + q * 16 + ks * 16 * BPN);
                    ldsm4t(bH + off, bh[q][0], bh[q][1], bh[q][2], bh[q][3]);
                    ldsm4t(bL + off, bl[q][0], bl[q][1], bl[q][2], bl[q][3]);
                }
            }
#pragma unroll
            for (int im = 0; im < 2; im++)
#pragma unroll
                for (int in = 0; in < 4; in++) {
                    int q = in >> 1, p = (in & 1) * 2;
                    MMAB(acc[im][in], al[im], bh[q][p], bh[q][p + 1]);
                    MMAB(acc[im][in], ah[im], bl[q][p], bl[q][p + 1]);
                    MMAB(acc[im][in], ah[im], bh[q][p], bh[q][p + 1]);
                }
        }

        if (more) {
            int nb = buf ^ 1;
#pragma unroll
            for (int i = 0; i < 4; i++) {
                int m = a_mr + 16 * i;
                split4(ra[i], Ahs[nb], Als[nb], m * AP + a_k4 * 4);
            }
            if (TRANSB) {
#pragma unroll
                for (int i = 0; i < 4; i++) {
                    int n = a_mr + 16 * i;
                    split4(rb[i], Bhs[nb], Bls[nb], n * AP + a_k4 * 4);
                }
            } else {
#pragma unroll
                for (int i = 0; i < 4; i++) {
                    int kk = bn_kr + 8 * i;
                    split4(rb[i], Bhs[nb], Bls[nb], kk * BPN + bn_n4 * 4);
                }
            }
        }
        __syncthreads();
        buf ^= 1;
    }

    float scv = SCALE ? scale[z1] : 1.f;
#pragma unroll
    for (int im = 0; im < 2; im++) {
        int r0 = m0 + wm * 32 + im * 16 + g;
        int r1 = r0 + 8;
#pragma unroll
        for (int in = 0; in < 4; in++) {
            int c = n0 + wn * 32 + in * 8 + 2 * tg;
            float b0 = 0.f, b1v = 0.f;
            if (BIAS) { b0 = bias[c]; b1v = bias[c + 1]; }
            float2 v0, v1;
            if (SCALE) {
                v0 = make_float2(acc[im][in][0] * scv, acc[im][in][1] * scv);
                v1 = make_float2(acc[im][in][2] * scv, acc[im][in][3] * scv);
            } else {
                v0 = make_float2(acc[im][in][0] + b0, acc[im][in][1] + b1v);
                v1 = make_float2(acc[im][in][2] + b0, acc[im][in][3] + b1v);
            }
            *(float2*)&C[(long)r0 * ldc + c] = v0;
            *(float2*)&C[(long)r1 * ldc + c] = v1;
        }
    }
#undef MMAB
}

// ---------------- init (clear histograms + maxes) ----------------
__global__ void init_kernel()
{
    int idx = blockIdx.x * 1024 + threadIdx.x;   // 128 x 1024 = 131072
    int b = idx >> 16, bin = idx & 65535;
    g_h16[b][bin] = 0u;
    if (idx < BB) g_mxu[idx] = 0u;
    if (idx < BB * HEADS) g_sjmx[idx] = 0u;
}

// ---------------- s_i, s_j + per-(b,h) max of s_j ----------------
__global__ void sij_kernel(const float* __restrict__ attn)
{
    int gw = (blockIdx.x * blockDim.x + threadIdx.x) >> 5;
    int lane = threadIdx.x & 31;
    if (gw >= BB * HEADS * NN_NODES) return;
    int b = gw / (HEADS * NN_NODES);
    int r = gw % (HEADS * NN_NODES);
    int h = r / NN_NODES;
    int n = r % NN_NODES;
    const float* hp = g_hp + ((long)(b * NN_NODES + n)) * FDIM + h * DH;
    const float* ai = attn + h * 2 * DH;
    float si = 0.f, sj = 0.f;
#pragma unroll
    for (int d = lane; d < DH; d += 32) {
        float v = hp[d];
        si += v * ai[d];
        sj += v * ai[DH + d];
    }
#pragma unroll
    for (int o = 16; o > 0; o >>= 1) {
        si += __shfl_down_sync(0xffffffffu, si, o);
        sj += __shfl_down_sync(0xffffffffu, sj, o);
    }
    if (lane == 0) {
        g_si[gw] = si;
        g_sj[gw] = sj;
        atomicMax(&g_sjmx[b * HEADS + h], enc_f(sj));
    }
}

// ---------------- attention softmax rows -> g_alpha ----------------
__global__ void alpha_kernel()
{
    __shared__ float sj[NN_NODES];
    int bh = blockIdx.y;
    int tid = threadIdx.x;
    for (int j = tid; j < NN_NODES; j += 256) sj[j] = g_sj[bh * NN_NODES + j];
    __syncthreads();

    int wrp = tid >> 5, lane = tid & 31;
    int i = blockIdx.x * 8 + wrp;
    float si = g_si[bh * NN_NODES + i];
    float sjmax = dec_f(g_sjmx[bh]);
    float M = si + sjmax;
    M = (M >= 0.f) ? M : 0.2f * M;   // leaky monotone -> row max
    float p[16];
    float sum = 0.f;
#pragma unroll
    for (int t = 0; t < 16; t++) {
        float e = si + sj[lane + 32 * t];
        e = (e >= 0.f) ? e : 0.2f * e;
        p[t] = expf(e - M);
        sum += p[t];
    }
#pragma unroll
    for (int o = 16; o > 0; o >>= 1) sum += __shfl_xor_sync(0xffffffffu, sum, o);
    float inv = 1.0f / sum;
    float* row = g_alpha + (long)bh * NN2 + (long)i * NN_NODES;
#pragma unroll
    for (int t = 0; t < 16; t++) row[lane + 32 * t] = p[t] * inv;
}

// ---------------- edge MLP scores + global max ----------------
__global__ void edge_kernel(const float* __restrict__ b1,
                            const float* __restrict__ w2,
                            const float* __restrict__ b2p)
{
    __shared__ float spi[16][260];
    __shared__ float spj[16][260];
    __shared__ float sw2[AH];
    __shared__ float red[256];
    int b = blockIdx.z;
    int i0 = blockIdx.y * 16, j0 = blockIdx.x * 16;
    int tid = threadIdx.x;

    float b1v = b1[tid];
    sw2[tid] = w2[tid];
#pragma unroll
    for (int l = 0; l < 16; l++) {
        spi[l][tid] = g_pij[((long)(b * NN_NODES) + i0 + l) * AH + tid] + b1v;
        spj[l][tid] = g_pij[PJOFF + ((long)(b * NN_NODES) + j0 + l) * AH + tid];
    }
    __syncthreads();
    int ti = tid >> 4, tj = tid & 15;
    float acc = 0.f;
#pragma unroll
    for (int a = 0; a < AH; a += 4) {
        float4 p4 = *(const float4*)&spi[ti][a];
        float4 q4 = *(const float4*)&spj[tj][a];
        float4 w4 = *(const float4*)&sw2[a];
        acc += fmaxf(p4.x + q4.x, 0.f) * w4.x;
        acc += fmaxf(p4.y + q4.y, 0.f) * w4.y;
        acc += fmaxf(p4.z + q4.z, 0.f) * w4.z;
        acc += fmaxf(p4.w + q4.w, 0.f) * w4.w;
    }
    float sc = (acc + b2p[0]) * 2.0f;   // /TEMP
    g_sc[(long)b * NN2 + (long)(i0 + ti) * NN_NODES + (j0 + tj)] = sc;

    red[tid] = sc;
    __syncthreads();
    for (int s = 128; s > 0; s >>= 1) {
        if (tid < s) red[tid] = fmaxf(red[tid], red[tid + s]);
        __syncthreads();
    }
    if (tid == 0) atomicMax(&g_mxu[b], enc_f(red[0]));
}

// ---------------- 2-level radix select on encoded scores ----------------
__global__ void histA_kernel()
{
    int b = blockIdx.y, blk = blockIdx.x, tid = threadIdx.x;
    const float* sm = g_sc + (long)b * NN2;
    for (int i = blk * 256 + tid; i < NN2; i += 32 * 256) {
        unsigned e = enc_f(sm[i]);
        atomicAdd(&g_h16[b][e >> 16], 1u);
    }
}
__global__ void histB_kernel()
{
    int b = blockIdx.y, blk = blockIdx.x, tid = threadIdx.x;
    unsigned hi = g_hi16[b];
    const float* sm = g_sc + (long)b * NN2;
    for (int i = blk * 256 + tid; i < NN2; i += 32 * 256) {
        unsigned e = enc_f(sm[i]);
        if ((e >> 16) == hi) atomicAdd(&g_h16[b][e & 0xFFFFu], 1u);
    }
}
__global__ void pick_kernel(int phase)
{
    __shared__ unsigned part[1024];
    __shared__ unsigned wsum[32];
    __shared__ int s_warp, s_thread;
    __shared__ unsigned s_base, s_base2;
    int b = blockIdx.x, tid = threadIdx.x, lane = tid & 31, wrp = tid >> 5;
    unsigned* bins = g_h16[b];
    unsigned rank = (phase == 0) ? (unsigned)THR_IDX : (unsigned)g_selrank[b];

    unsigned s = 0;
#pragma unroll 8
    for (int t = 0; t < 64; t++) s += bins[tid * 64 + t];
    part[tid] = s;
    unsigned wsv = s;
#pragma unroll
    for (int o = 16; o > 0; o >>= 1) wsv += __shfl_down_sync(0xffffffffu, wsv, o);
    if (lane == 0) wsum[wrp] = wsv;
    __syncthreads();

    if (tid == 0) {
        unsigned cum = 0; int w = 0;
        for (; w < 32; w++) { if (cum + wsum[w] > rank) break; cum += wsum[w]; }
        s_warp = w; s_base = cum;
    }
    __syncthreads();
    if (tid == s_warp * 32) {
        unsigned cum = s_base; int t = s_warp * 32;
        for (;; t++) { if (cum + part[t] > rank) break; cum += part[t]; }
        s_thread = t; s_base2 = cum;
    }
    __syncthreads();
    if (tid == s_thread) {
        unsigned cum = s_base2; int bin = tid * 64;
        for (;; bin++) { if (cum + bins[bin] > rank) break; cum += bins[bin]; }
        if (phase == 0) { g_hi16[b] = (unsigned)bin; g_selrank[b] = (int)(rank - cum); }
        else g_thrE[b] = (g_hi16[b] << 16) | (unsigned)bin;
    }
    __syncthreads();
    if (phase == 0) {
#pragma unroll 8
        for (int t = 0; t < 64; t++) bins[tid * 64 + t] = 0u;
    }
}

// ---------------- threshold + exp + partial sum ----------------
__global__ void thresh_kernel()
{
    int b = blockIdx.y, blk = blockIdx.x, tid = threadIdx.x;
    const float* sm = g_sc + (long)b * NN2;
    float* adj = g_adj + (long)b * NN2;
    float mx = dec_f(g_mxu[b]);
    unsigned thr = g_thrE[b];
    float s = 0.f;
    for (int i = blk * 256 + tid; i < NN2; i += 64 * 256) {
        float v = sm[i];
        unsigned e = enc_f(v);
        float keep = (e >= thr) ? expf(v - mx) : 0.f;
        adj[i] = keep;
        s += keep;
    }
    __shared__ float sh[256];
    sh[tid] = s; __syncthreads();
    for (int q = 128; q > 0; q >>= 1) { if (tid < q) sh[tid] += sh[tid + q]; __syncthreads(); }
    if (tid == 0) g_part[b * 64 + blk] = sh[0];
}
__global__ void inv_kernel()
{
    __shared__ float sh[64];
    int b = blockIdx.x, tid = threadIdx.x; // 64 threads
    sh[tid] = g_part[b * 64 + tid];
    __syncthreads();
    for (int q = 32; q > 0; q >>= 1) { if (tid < q) sh[tid] += sh[tid + q]; __syncthreads(); }
    if (tid == 0) g_inv[b] = 1.0f / sh[0];
}

// ---------------- batchnorm + relu ----------------
__global__ void bn_relu_kernel(float* __restrict__ h,
                               const float* __restrict__ ga,
                               const float* __restrict__ be, int C)
{
    __shared__ float sh[8][32], sh2[8][32];
    int c = blockIdx.x * 32 + threadIdx.x;
    int ry = threadIdx.y;
    float s = 0.f, s2 = 0.f;
    for (int r = ry; r < BN_M; r += 8) {
        float v = h[(long)r * C + c];
        s += v; s2 += v * v;
    }
    sh[ry][threadIdx.x] = s; sh2[ry][threadIdx.x] = s2;
    __syncthreads();
    if (ry == 0) {
        for (int r = 1; r < 8; r++) { s += sh[r][threadIdx.x]; s2 += sh2[r][threadIdx.x]; }
        float m = s / (float)BN_M;
        float v = s2 / (float)BN_M - m * m;
        sh[0][threadIdx.x] = m;
        sh2[0][threadIdx.x] = rsqrtf(v + 1e-5f);
    }
    __syncthreads();
    float m = sh[0][threadIdx.x], inv = sh2[0][threadIdx.x];
    float gg = ga[c], bb = be[c];
    for (int r = ry; r < BN_M; r += 8) {
        float v = h[(long)r * C + c];
        h[(long)r * C + c] = fmaxf((v - m) * inv * gg + bb, 0.f);
    }
}

// ---------------- mean pool + classifier ----------------
__global__ void head_kernel(const float* __restrict__ cls_w,
                            const float* __restrict__ cls_b,
                            float* __restrict__ out)
{
    __shared__ float acc4[4][OUTF];
    __shared__ float feat[OUTF];
    int b = blockIdx.x, tid = threadIdx.x; // 512 threads
    int r0 = tid >> 7, f = tid & 127;
    float s = 0.f;
    for (int r = r0; r < NN_NODES; r += 4)
        s += g_h2b[((long)b * NN_NODES + r) * OUTF + f];
    acc4[r0][f] = s;
    __syncthreads();
    if (tid < OUTF)
        feat[tid] = (acc4[0][tid] + acc4[1][tid] + acc4[2][tid] + acc4[3][tid]) / (float)NN_NODES;
    __syncthreads();
    if (tid < NCLS) {
        float acc = cls_b[tid];
        for (int ff = 0; ff < OUTF; ff++) acc += feat[ff] * cls_w[tid * OUTF + ff];
        out[b * NCLS + tid] = acc;
    }
}

// ---------------- launcher ----------------
extern "C" void kernel_launch(void* const* d_in, const int* in_sizes, int n_in,
                              void* d_out, int out_size)
{
    const float* x     = (const float*)d_in[0];
    const float* Wg    = (const float*)d_in[1];
    const float* attn  = (const float*)d_in[2];
    const float* W1    = (const float*)d_in[3];
    const float* b1    = (const float*)d_in[4];
    const float* w2    = (const float*)d_in[5];
    const float* b2    = (const float*)d_in[6];
    const float* gc1_w = (const float*)d_in[7];
    const float* gc1_b = (const float*)d_in[8];
    const float* bn1_g = (const float*)d_in[9];
    const float* bn1_b = (const float*)d_in[10];
    const float* gc2_w = (const float*)d_in[11];
    const float* gc2_b = (const float*)d_in[12];
    const float* bn2_g = (const float*)d_in[13];
    const float* bn2_b = (const float*)d_in[14];
    const float* cls_w = (const float*)d_in[15];
    const float* cls_b = (const float*)d_in[16];
    float* out = (float*)d_out;

    float *hp, *nf, *alpha, *pij, *adj, *h1, *h1b, *h2, *h2b, *ginv;
    cudaGetSymbolAddress((void**)&hp,  g_hp);
    cudaGetSymbolAddress((void**)&nf,  g_nf);
    cudaGetSymbolAddress((void**)&alpha, g_alpha);
    cudaGetSymbolAddress((void**)&pij, g_pij);
    cudaGetSymbolAddress((void**)&adj, g_adj);
    cudaGetSymbolAddress((void**)&h1,  g_h1);
    cudaGetSymbolAddress((void**)&h1b, g_h1b);
    cudaGetSymbolAddress((void**)&h2,  g_h2);
    cudaGetSymbolAddress((void**)&h2b, g_h2b);
    cudaGetSymbolAddress((void**)&ginv, g_inv);

    init_kernel<<<128, 1024>>>();

    // 1) hp = x @ Wg^T
    mma_gemm<true, false, false><<<dim3(16, 16, 1), 128>>>(
        x, FDIM, 0, 0, Wg, FDIM, 0, 0, nullptr, nullptr, hp, FDIM, 0, 0, FDIM, 1);

    // 2) s_i, s_j + sjmax
    sij_kernel<<<(BB * HEADS * NN_NODES * 32 + 255) / 256, 256>>>(attn);

    // 3a) softmax rows -> alpha
    alpha_kernel<<<dim3(NN_NODES / 8, BB * HEADS), 256>>>();

    // 3b) nf[b,:,h*DH:(h+1)*DH] = alpha[bh] @ hp[b,:,h*DH:(h+1)*DH]
    mma_gemm<false, false, false><<<dim3(DH / 64, NN_NODES / 64, BB * HEADS), 128>>>(
        alpha, NN_NODES, (long)HEADS * NN2, (long)NN2,
        hp, FDIM, (long)NN_NODES * FDIM, (long)DH,
        nullptr, nullptr,
        nf, FDIM, (long)NN_NODES * FDIM, (long)DH, NN_NODES, HEADS);

    // 4) pi/pj fused (grid.z picks W1 half and output half)
    mma_gemm<true, false, false><<<dim3(AH / 64, 16, 2), 128>>>(
        nf, FDIM, 0, 0, W1, 2 * FDIM, FDIM, 0, nullptr, nullptr,
        pij, AH, (long)PJOFF, 0, FDIM, 1);

    // 5) edge scores + global max
    edge_kernel<<<dim3(NN_NODES / 16, NN_NODES / 16, BB), 256>>>(b1, w2, b2);

    // 6) exact k-th order statistic on raw scores (2-level 16-bit radix)
    histA_kernel<<<dim3(32, BB), 256>>>();
    pick_kernel<<<BB, 1024>>>(0);
    histB_kernel<<<dim3(32, BB), 256>>>();
    pick_kernel<<<BB, 1024>>>(1);

    // 7) threshold + exp + sum -> 1/denom
    thresh_kernel<<<dim3(64, BB), 256>>>();
    inv_kernel<<<BB, 64>>>();

    // 8) h1 = (adjU @ nf) * inv[b]
    mma_gemm<false, false, true><<<dim3(FDIM / 64, NN_NODES / 64, BB), 128>>>(
        adj, NN_NODES, (long)NN2, 0, nf, FDIM, (long)NN_NODES * FDIM, 0,
        nullptr, ginv, h1, FDIM, (long)NN_NODES * FDIM, 0, NN_NODES, 1);

    // 9) h1b = h1 @ gc1_w^T + gc1_b
    mma_gemm<true, true, false><<<dim3(HID / 64, 16, 1), 128>>>(
        h1, FDIM, 0, 0, gc1_w, FDIM, 0, 0, gc1_b, nullptr, h1b, HID, 0, 0, FDIM, 1);

    // 10) bn1 + relu
    bn_relu_kernel<<<HID / 32, dim3(32, 8)>>>(h1b, bn1_g, bn1_b, HID);

    // 11) h2 = (adjU @ h1b) * inv[b]
    mma_gemm<false, false, true><<<dim3(HID / 64, NN_NODES / 64, BB), 128>>>(
        adj, NN_NODES, (long)NN2, 0, h1b, HID, (long)NN_NODES * HID, 0,
        nullptr, ginv, h2, HID, (long)NN_NODES * HID, 0, NN_NODES, 1);

    // 12) h2b = h2 @ gc2_w^T + gc2_b
    mma_gemm<true, true, false><<<dim3(OUTF / 64, 16, 1), 128>>>(
        h2, HID, 0, 0, gc2_w, HID, 0, 0, gc2_b, nullptr, h2b, OUTF, 0, 0, HID, 1);

    // 13) bn2 + relu
    bn_relu_kernel<<<OUTF / 32, dim3(32, 8)>>>(h2b, bn2_g, bn2_b, OUTF);

    // 14) mean pool + classifier
    head_kernel<<<BB, 512>>>(cls_w, cls_b, out);
}